// round 4
// baseline (speedup 1.0000x reference)
#include <cuda_runtime.h>
#include <math.h>

// Model dims
#define NB   2
#define NT   2048
#define ND   768
#define NH   12
#define NHS  64
#define NL   6
#define NV   50257
#define NTOK (NB*NT)        // 4096
#define NQKV (3*ND)         // 2304
#define NFF  (4*ND)         // 3072

// ---------------- scratch (static device memory; no allocations) -----------
__device__ float g_x[NTOK*ND];
__device__ float g_h[NTOK*ND];
__device__ float g_qkv[(size_t)NTOK*NQKV];
__device__ float g_o[NTOK*ND];
__device__ float g_mlp[(size_t)NTOK*NFF];
__device__ float g_wqkv[(size_t)NL*ND*NQKV];
__device__ float g_loss;

// ---------------- small utility kernels ------------------------------------
__global__ void reset_loss_kernel() { g_loss = 0.0f; }

__global__ void repack_qkv_kernel(const float* __restrict__ wq,
                                  const float* __restrict__ wk,
                                  const float* __restrict__ wv) {
    int i = blockIdx.x * 256 + threadIdx.x;
    const int total = NL * ND * NQKV;
    if (i >= total) return;
    int c = i % NQKV;
    int d = (i / NQKV) % ND;
    int l = i / (NQKV * ND);
    int sec = c / ND;            // 0=q, 1=k, 2=v
    int c2  = c % ND;
    int h   = c2 / NHS;
    int e   = c2 % NHS;
    const float* w = (sec == 0) ? wq : (sec == 1) ? wk : wv;
    g_wqkv[i] = w[(((size_t)l * NH + h) * ND + d) * NHS + e];
}

__global__ void embed_kernel(const int* __restrict__ idx,
                             const float* __restrict__ tok,
                             const float* __restrict__ pos) {
    int i = blockIdx.x * 256 + threadIdx.x;
    if (i >= NTOK * ND) return;
    int d = i % ND;
    int row = i / ND;         // b*NT + t
    int t = row % NT;
    int tokid = idx[row];
    g_x[i] = tok[(size_t)tokid * ND + d] + pos[t * ND + d];
}

// ---------------- layernorm: one block (256 thr) per row, D=768 ------------
__global__ __launch_bounds__(256)
void ln_kernel(const float* __restrict__ x, const float* __restrict__ s,
               const float* __restrict__ b, float* __restrict__ out) {
    __shared__ float red[256];
    int row = blockIdx.x, tid = threadIdx.x;
    const float* xr = x + (size_t)row * ND;
    float v0 = xr[tid], v1 = xr[tid + 256], v2 = xr[tid + 512];
    red[tid] = v0 + v1 + v2;
    __syncthreads();
    for (int off = 128; off; off >>= 1) {
        if (tid < off) red[tid] += red[tid + off];
        __syncthreads();
    }
    float mean = red[0] * (1.0f / ND);
    __syncthreads();
    float d0 = v0 - mean, d1 = v1 - mean, d2 = v2 - mean;
    red[tid] = d0 * d0 + d1 * d1 + d2 * d2;
    __syncthreads();
    for (int off = 128; off; off >>= 1) {
        if (tid < off) red[tid] += red[tid + off];
        __syncthreads();
    }
    float rstd = rsqrtf(red[0] * (1.0f / ND) + 1e-5f);
    float* orow = out + (size_t)row * ND;
    orow[tid]       = d0 * rstd * s[tid]       + b[tid];
    orow[tid + 256] = d1 * rstd * s[tid + 256] + b[tid + 256];
    orow[tid + 512] = d2 * rstd * s[tid + 512] + b[tid + 512];
}

// ---------------- TF32 tensor-core GEMM (double-buffered) -------------------
// C[MxN] = A[MxK] @ B[KxN] (+bias, +relu, +resid)
// Block 128x128, BK=16, 128 threads = 4 warps (2x2), warp tile 64x64.
// Double-buffered smem, ONE __syncthreads per k-tile.
// Grid: blockIdx.x = M panel (fast), blockIdx.y = N panel (slow) so a wave
// reuses one B column-panel across all M panels (L2 reuse for the LM head).
// M multiple of 128, K multiple of 16; N may be ragged and odd (V=50257).

__device__ __forceinline__ unsigned f2tf(float x) {
    unsigned u;
    asm("cvt.rna.tf32.f32 %0, %1;" : "=r"(u) : "f"(x));
    return u;
}

#define SMP 136            // padded smem row stride (words)
#define ASZ (16*SMP)       // words per stage per matrix

template <int EPI>  // bit0: +bias[n], bit1: relu, bit2: +resid[m,n]
__global__ __launch_bounds__(128)
void mma_gemm(const float* __restrict__ A, const float* __restrict__ B,
              const float* __restrict__ bias, const float* __restrict__ resid,
              float* __restrict__ C, int M, int N, int K) {
    __shared__ unsigned As[2 * ASZ];
    __shared__ unsigned Bs[2 * ASZ];
    const int tid  = threadIdx.x;
    const int lane = tid & 31;
    const int warp = tid >> 5;
    const int wm = (warp >> 1) * 64;   // warp row offset within block
    const int wn = (warp & 1) * 64;    // warp col offset within block
    const int row0 = blockIdx.x * 128, col0 = blockIdx.y * 128;
    const bool bvec = ((N & 3) == 0) && (col0 + 128 <= N);

    float acc[4][8][4];
#pragma unroll
    for (int mf = 0; mf < 4; mf++)
#pragma unroll
        for (int nf = 0; nf < 8; nf++)
#pragma unroll
            for (int j = 0; j < 4; j++) acc[mf][nf][j] = 0.0f;

    // A: thread tid loads row (row0+tid), k-chunk of 16 (4 float4)
    // B: items tid*4+i -> k=(tid*4+i)>>5 (same for i=0..3), nc=(tid*4)&31 + i
    float4 pa[4];
    float  pb[4][4];
    const int bk  = (tid * 4) >> 5;
    const int bn0 = (tid * 4) & 31;
    const float* Arow = A + (size_t)(row0 + tid) * K;
    const int KT = K / 16;

#define LOAD_A(k0)                                                          \
    {                                                                       \
        _Pragma("unroll")                                                   \
        for (int i = 0; i < 4; i++)                                         \
            pa[i] = *reinterpret_cast<const float4*>(Arow + (k0) + i * 4);  \
    }
#define LOAD_B(k0)                                                          \
    {                                                                       \
        const float* brow = B + (size_t)((k0) + bk) * N + col0;             \
        if (bvec) {                                                         \
            _Pragma("unroll")                                               \
            for (int i = 0; i < 4; i++) {                                   \
                float4 v = *reinterpret_cast<const float4*>(brow + (bn0 + i) * 4); \
                pb[i][0] = v.x; pb[i][1] = v.y; pb[i][2] = v.z; pb[i][3] = v.w; \
            }                                                               \
        } else {                                                            \
            _Pragma("unroll")                                               \
            for (int i = 0; i < 4; i++) {                                   \
                _Pragma("unroll")                                           \
                for (int j = 0; j < 4; j++) {                               \
                    int n = col0 + (bn0 + i) * 4 + j;                       \
                    pb[i][j] = (n < N) ? brow[(bn0 + i) * 4 + j] : 0.0f;    \
                }                                                           \
            }                                                               \
        }                                                                   \
    }
#define STORE_SM(st)                                                        \
    {                                                                       \
        unsigned* as = As + (st) * ASZ;                                     \
        unsigned* bs = Bs + (st) * ASZ;                                     \
        _Pragma("unroll")                                                   \
        for (int i = 0; i < 4; i++) {                                       \
            as[(i * 4 + 0) * SMP + tid] = f2tf(pa[i].x);                    \
            as[(i * 4 + 1) * SMP + tid] = f2tf(pa[i].y);                    \
            as[(i * 4 + 2) * SMP + tid] = f2tf(pa[i].z);                    \
            as[(i * 4 + 3) * SMP + tid] = f2tf(pa[i].w);                    \
        }                                                                   \
        _Pragma("unroll")                                                   \
        for (int i = 0; i < 4; i++) {                                       \
            uint4 v = make_uint4(f2tf(pb[i][0]), f2tf(pb[i][1]),            \
                                 f2tf(pb[i][2]), f2tf(pb[i][3]));           \
            *reinterpret_cast<uint4*>(bs + bk * SMP + (bn0 + i) * 4) = v;   \
        }                                                                   \
    }

    LOAD_A(0); LOAD_B(0); STORE_SM(0);
    __syncthreads();

    for (int kt = 0; kt < KT; kt++) {
        const int st = kt & 1;
        if (kt + 1 < KT) { LOAD_A((kt + 1) * 16); LOAD_B((kt + 1) * 16); }

        const unsigned* as = As + st * ASZ;
        const unsigned* bs = Bs + st * ASZ;
#pragma unroll
        for (int ks = 0; ks < 16; ks += 8) {
            unsigned af[4][4], bf[8][2];
            const int kq = ks + (lane & 3);
            const int g  = lane >> 2;
#pragma unroll
            for (int mf = 0; mf < 4; mf++) {
                int m = wm + mf * 16 + g;
                af[mf][0] = as[kq * SMP + m];
                af[mf][1] = as[kq * SMP + m + 8];
                af[mf][2] = as[(kq + 4) * SMP + m];
                af[mf][3] = as[(kq + 4) * SMP + m + 8];
            }
#pragma unroll
            for (int nf = 0; nf < 8; nf++) {
                int n = wn + nf * 8 + g;
                bf[nf][0] = bs[kq * SMP + n];
                bf[nf][1] = bs[(kq + 4) * SMP + n];
            }
#pragma unroll
            for (int mf = 0; mf < 4; mf++)
#pragma unroll
                for (int nf = 0; nf < 8; nf++)
                    asm volatile(
                        "mma.sync.aligned.m16n8k8.row.col.f32.tf32.tf32.f32 "
                        "{%0,%1,%2,%3}, {%4,%5,%6,%7}, {%8,%9}, {%0,%1,%2,%3};"
                        : "+f"(acc[mf][nf][0]), "+f"(acc[mf][nf][1]),
                          "+f"(acc[mf][nf][2]), "+f"(acc[mf][nf][3])
                        : "r"(af[mf][0]), "r"(af[mf][1]), "r"(af[mf][2]), "r"(af[mf][3]),
                          "r"(bf[nf][0]), "r"(bf[nf][1]));
        }

        if (kt + 1 < KT) {
            STORE_SM(st ^ 1);
            __syncthreads();
        }
    }

    // epilogue: c0=(r,n) c1=(r,n+1) c2=(r+8,n) c3=(r+8,n+1)
#pragma unroll
    for (int mf = 0; mf < 4; mf++) {
        int r0 = row0 + wm + mf * 16 + (lane >> 2);
#pragma unroll
        for (int nf = 0; nf < 8; nf++) {
            int n0 = col0 + wn + nf * 8 + 2 * (lane & 3);
#pragma unroll
            for (int half = 0; half < 2; half++) {
                int r = r0 + half * 8;
#pragma unroll
                for (int j = 0; j < 2; j++) {
                    int n = n0 + j;
                    if (n < N) {
                        float v = acc[mf][nf][half * 2 + j];
                        if (EPI & 1) v += bias[n];
                        if (EPI & 2) v = fmaxf(v, 0.0f);
                        if (EPI & 4) v += resid[(size_t)r * N + n];
                        C[(size_t)r * N + n] = v;
                    }
                }
            }
        }
    }
#undef LOAD_A
#undef LOAD_B
#undef STORE_SM
}

// ---------------- streaming causal attention (warp = 4 queries) ------------
__global__ __launch_bounds__(256)
void attn_kernel(const float* __restrict__ qkv, float* __restrict__ o) {
    int wid = blockIdx.x * 8 + (threadIdx.x >> 5);
    int lane = threadIdx.x & 31;
    const int warps_per_head = NT / 4;  // 512
    int bh = wid / warps_per_head;
    int t0 = (wid % warps_per_head) * 4;
    int b = bh / NH, h = bh % NH;

    const float* base = qkv + (size_t)b * NT * NQKV;
    const float* qb = base + h * NHS;
    const float* kb = base + ND + h * NHS;
    const float* vb = base + 2 * ND + h * NHS;

    float q0[4], q1[4];
#pragma unroll
    for (int i = 0; i < 4; i++) {
        q0[i] = qb[(size_t)(t0 + i) * NQKV + lane];
        q1[i] = qb[(size_t)(t0 + i) * NQKV + 32 + lane];
    }
    float m[4], l[4], a0[4], a1[4];
#pragma unroll
    for (int i = 0; i < 4; i++) { m[i] = -1e30f; l[i] = 0.f; a0[i] = 0.f; a1[i] = 0.f; }

    const float scale = 0.125f;  // HS^-0.5
    int send = t0 + 3;
    for (int s = 0; s <= send; s++) {
        size_t off = (size_t)s * NQKV + lane;
        float k0v = kb[off], k1v = kb[off + 32];
        float v0v = vb[off], v1v = vb[off + 32];
#pragma unroll
        for (int i = 0; i < 4; i++) {
            float p = q0[i] * k0v + q1[i] * k1v;
            p += __shfl_xor_sync(0xffffffffu, p, 16);
            p += __shfl_xor_sync(0xffffffffu, p, 8);
            p += __shfl_xor_sync(0xffffffffu, p, 4);
            p += __shfl_xor_sync(0xffffffffu, p, 2);
            p += __shfl_xor_sync(0xffffffffu, p, 1);
            if (s <= t0 + i) {
                float sc = p * scale;
                float mn = fmaxf(m[i], sc);
                float corr = __expf(m[i] - mn);
                float e = __expf(sc - mn);
                l[i]  = l[i]  * corr + e;
                a0[i] = a0[i] * corr + e * v0v;
                a1[i] = a1[i] * corr + e * v1v;
                m[i] = mn;
            }
        }
    }
#pragma unroll
    for (int i = 0; i < 4; i++) {
        size_t oo = (size_t)(b * NT + t0 + i) * ND + h * NHS + lane;
        o[oo]      = a0[i] / l[i];
        o[oo + 32] = a1[i] / l[i];
    }
}

// ---------------- loss: one block per row over V=50257 ---------------------
__global__ __launch_bounds__(256)
void loss_kernel(const float* __restrict__ logits, const int* __restrict__ targets) {
    __shared__ float sm_[256], sl_[256];
    int row = blockIdx.x, tid = threadIdx.x;
    const float* lr = logits + (size_t)row * NV;
    float m = -1e30f, l = 0.0f;
    for (int j = tid; j < NV; j += 256) {
        float v = lr[j];
        float mn = fmaxf(m, v);
        l = l * __expf(m - mn) + __expf(v - mn);
        m = mn;
    }
    sm_[tid] = m; sl_[tid] = l;
    __syncthreads();
    for (int off = 128; off; off >>= 1) {
        if (tid < off) {
            float m2 = sm_[tid + off], l2 = sl_[tid + off];
            float mn = fmaxf(sm_[tid], m2);
            sl_[tid] = sl_[tid] * __expf(sm_[tid] - mn) + l2 * __expf(m2 - mn);
            sm_[tid] = mn;
        }
        __syncthreads();
    }
    if (tid == 0) {
        float lp = lr[targets[row]] - sm_[0] - logf(sl_[0]);
        atomicAdd(&g_loss, -lp * (1.0f / NTOK));
    }
}

__global__ void finalize_loss_kernel(float* out, int out_size) {
    long long pos = (long long)NTOK * NV;
    if ((long long)out_size > pos) out[pos] = g_loss;
}

// ---------------- host orchestration ----------------------------------------
extern "C" void kernel_launch(void* const* d_in, const int* in_sizes, int n_in,
                              void* d_out, int out_size) {
    const int*   idx     = (const int*)d_in[0];
    const int*   targets = (const int*)d_in[1];
    const float* tok_emb = (const float*)d_in[2];
    const float* pos_emb = (const float*)d_in[3];
    const float* wq      = (const float*)d_in[4];
    const float* wk      = (const float*)d_in[5];
    const float* wv      = (const float*)d_in[6];
    const float* wo      = (const float*)d_in[7];
    const float* bo      = (const float*)d_in[8];
    const float* ln1_s   = (const float*)d_in[9];
    const float* ln1_b   = (const float*)d_in[10];
    const float* ln2_s   = (const float*)d_in[11];
    const float* ln2_b   = (const float*)d_in[12];
    const float* w1      = (const float*)d_in[13];
    const float* b1      = (const float*)d_in[14];
    const float* w2      = (const float*)d_in[15];
    const float* b2      = (const float*)d_in[16];
    const float* lnf_s   = (const float*)d_in[17];
    const float* lnf_b   = (const float*)d_in[18];
    const float* head_w  = (const float*)d_in[19];
    const float* head_b  = (const float*)d_in[20];
    float* out = (float*)d_out;
    (void)in_sizes; (void)n_in;

    float *px, *ph, *pqkv, *po, *pmlp, *pw;
    cudaGetSymbolAddress((void**)&px,   g_x);
    cudaGetSymbolAddress((void**)&ph,   g_h);
    cudaGetSymbolAddress((void**)&pqkv, g_qkv);
    cudaGetSymbolAddress((void**)&po,   g_o);
    cudaGetSymbolAddress((void**)&pmlp, g_mlp);
    cudaGetSymbolAddress((void**)&pw,   g_wqkv);

    reset_loss_kernel<<<1, 1>>>();
    {
        int total = NL * ND * NQKV;
        repack_qkv_kernel<<<(total + 255) / 256, 256>>>(wq, wk, wv);
    }
    {
        int total = NTOK * ND;
        embed_kernel<<<(total + 255) / 256, 256>>>(idx, tok_emb, pos_emb);
    }

    // grid: x = M panels (fast), y = N panels (slow) for B-panel L2 reuse
    dim3 gQKV(NTOK / 128, (NQKV + 127) / 128);
    dim3 gD(NTOK / 128, (ND + 127) / 128);
    dim3 gFF(NTOK / 128, (NFF + 127) / 128);
    dim3 gV(NTOK / 128, (NV + 127) / 128);

    for (int l = 0; l < NL; l++) {
        ln_kernel<<<NTOK, 256>>>(px, ln1_s + l * ND, ln1_b + l * ND, ph);
        mma_gemm<0><<<gQKV, 128>>>(ph, pw + (size_t)l * ND * NQKV,
                                   nullptr, nullptr, pqkv, NTOK, NQKV, ND);
        attn_kernel<<<NB * NH * NT / 4 / 8, 256>>>(pqkv, po);
        mma_gemm<5><<<gD, 128>>>(po, wo + (size_t)l * ND * ND,
                                 bo + l * ND, px, px, NTOK, ND, ND);
        ln_kernel<<<NTOK, 256>>>(px, ln2_s + l * ND, ln2_b + l * ND, ph);
        mma_gemm<3><<<gFF, 128>>>(ph, w1 + (size_t)l * ND * NFF,
                                  b1 + l * NFF, nullptr, pmlp, NTOK, NFF, ND);
        mma_gemm<5><<<gD, 128>>>(pmlp, w2 + (size_t)l * NFF * ND,
                                 b2 + l * ND, px, px, NTOK, ND, NFF);
    }

    ln_kernel<<<NTOK, 256>>>(px, lnf_s, lnf_b, ph);
    mma_gemm<1><<<gV, 128>>>(ph, head_w, head_b, nullptr, out, NTOK, NV, ND);
    loss_kernel<<<NTOK, 256>>>(out, targets);
    finalize_loss_kernel<<<1, 1>>>(out, out_size);
}

// round 6
// speedup vs baseline: 1.1422x; 1.1422x over previous
#include <cuda_runtime.h>
#include <cuda_fp16.h>
#include <math.h>
#include <stdint.h>

// Model dims
#define NB   2
#define NT   2048
#define ND   768
#define NH   12
#define NHS  64
#define NL   6
#define NV   50257
#define NTOK (NB*NT)        // 4096
#define NQKV (3*ND)         // 2304
#define NFF  (4*ND)         // 3072

// ---------------- scratch (static device memory; no allocations) -----------
__device__ float g_x[NTOK*ND];
__device__ float g_h[NTOK*ND];
__device__ float g_qkv[(size_t)NTOK*NQKV];
__device__ float g_o[NTOK*ND];
__device__ float g_mlp[(size_t)NTOK*NFF];
__device__ float g_wqkvT[(size_t)NL*NQKV*ND];     // [l][n][k]
__device__ float g_woT [(size_t)NL*ND*ND];        // [l][n][k]
__device__ float g_w1T [(size_t)NL*NFF*ND];       // [l][n][k]
__device__ float g_w2T [(size_t)NL*ND*NFF];       // [l][n][k]
__device__ float g_headT[(size_t)NV*ND];          // [n][k]
__device__ float g_loss;

// ---------------- small utility kernels ------------------------------------
__global__ void reset_loss_kernel() { g_loss = 0.0f; }

// gather QKV weights transposed: g_wqkvT[(l*NQKV + c)*ND + d]
__global__ void repack_qkv_kernel(const float* __restrict__ wq,
                                  const float* __restrict__ wk,
                                  const float* __restrict__ wv) {
    int i = blockIdx.x * 256 + threadIdx.x;
    const int total = NL * NQKV * ND;
    if (i >= total) return;
    int d = i % ND;
    int c = (i / ND) % NQKV;
    int l = i / (ND * NQKV);
    int sec = c / ND;            // 0=q, 1=k, 2=v
    int c2  = c % ND;
    int h   = c2 / NHS;
    int e   = c2 % NHS;
    const float* w = (sec == 0) ? wq : (sec == 1) ? wk : wv;
    g_wqkvT[i] = w[(((size_t)l * NH + h) * ND + d) * NHS + e];
}

// generic batched transpose: src [batch][R][C] -> dst [batch][C][R]
__global__ void transpose_kernel(const float* __restrict__ src,
                                 float* __restrict__ dst, int R, int C) {
    __shared__ float t[32][33];
    size_t boff = (size_t)blockIdx.z * R * C;
    int c0 = blockIdx.x * 32, r0 = blockIdx.y * 32;
#pragma unroll
    for (int i = 0; i < 32; i += 8) {
        int x = c0 + threadIdx.x, y = r0 + threadIdx.y + i;
        if (x < C && y < R) t[threadIdx.y + i][threadIdx.x] = src[boff + (size_t)y * C + x];
    }
    __syncthreads();
#pragma unroll
    for (int i = 0; i < 32; i += 8) {
        int x = r0 + threadIdx.x, y = c0 + threadIdx.y + i;
        if (x < R && y < C) dst[boff + (size_t)y * R + x] = t[threadIdx.x][threadIdx.y + i];
    }
}

__global__ void embed_kernel(const int* __restrict__ idx,
                             const float* __restrict__ tok,
                             const float* __restrict__ pos) {
    int i = blockIdx.x * 256 + threadIdx.x;
    if (i >= NTOK * ND) return;
    int d = i % ND;
    int row = i / ND;
    int t = row % NT;
    int tokid = idx[row];
    g_x[i] = tok[(size_t)tokid * ND + d] + pos[t * ND + d];
}

// ---------------- layernorm -------------------------------------------------
__global__ __launch_bounds__(256)
void ln_kernel(const float* __restrict__ x, const float* __restrict__ s,
               const float* __restrict__ b, float* __restrict__ out) {
    __shared__ float red[256];
    int row = blockIdx.x, tid = threadIdx.x;
    const float* xr = x + (size_t)row * ND;
    float v0 = xr[tid], v1 = xr[tid + 256], v2 = xr[tid + 512];
    red[tid] = v0 + v1 + v2;
    __syncthreads();
    for (int off = 128; off; off >>= 1) {
        if (tid < off) red[tid] += red[tid + off];
        __syncthreads();
    }
    float mean = red[0] * (1.0f / ND);
    __syncthreads();
    float d0 = v0 - mean, d1 = v1 - mean, d2 = v2 - mean;
    red[tid] = d0 * d0 + d1 * d1 + d2 * d2;
    __syncthreads();
    for (int off = 128; off; off >>= 1) {
        if (tid < off) red[tid] += red[tid + off];
        __syncthreads();
    }
    float rstd = rsqrtf(red[0] * (1.0f / ND) + 1e-5f);
    float* orow = out + (size_t)row * ND;
    orow[tid]       = d0 * rstd * s[tid]       + b[tid];
    orow[tid + 256] = d1 * rstd * s[tid + 256] + b[tid + 256];
    orow[tid + 512] = d2 * rstd * s[tid + 512] + b[tid + 512];
}

// ---------------- FP16 tensor-core GEMM -------------------------------------
// C[MxN] = A[MxK] @ Bt[NxK]^T  (+bias, +relu, +resid)
// Block 128x128, BK=16, 256 threads = 8 warps (2x4), warp tile 64x32.
// mma.sync.aligned.m16n8k16.row.col.f32.f16.f16.f32 (2048 MACs/instr).
// Both smem tiles K-contiguous: As[m][k], Bs[n][k], row stride 24 halves
// (m*12 + (lane&3)) mod 32 covers all banks -> conflict-free fragment loads.
// M multiple of 128, K multiple of 16; N ragged-row safe (Bt rows guarded).

#define HSTR 24   // halves per smem row

template <int EPI>  // bit0: +bias[n], bit1: relu, bit2: +resid[m,n]
__global__ __launch_bounds__(256)
void hgemm(const float* __restrict__ A, const float* __restrict__ Bt,
           const float* __restrict__ bias, const float* __restrict__ resid,
           float* __restrict__ C, int M, int N, int K) {
    __shared__ __align__(16) __half As[128 * HSTR];
    __shared__ __align__(16) __half Bs[128 * HSTR];
    const int tid  = threadIdx.x;
    const int lane = tid & 31;
    const int warp = tid >> 5;
    const int wm = (warp >> 2) * 64;   // warp row offset
    const int wn = (warp & 3) * 32;    // warp col offset
    const int row0 = blockIdx.x * 128, col0 = blockIdx.y * 128;

    float acc[4][4][4];
#pragma unroll
    for (int mf = 0; mf < 4; mf++)
#pragma unroll
        for (int nf = 0; nf < 4; nf++)
#pragma unroll
            for (int j = 0; j < 4; j++) acc[mf][nf][j] = 0.0f;

    // load mapping: item idx = tid*2+i -> smem row r = idx>>2, f4-col kc = idx&3
    float4 pa[2], pb[2];
    const int KT = K / 16;

#define LOADT(k0)                                                             \
    {                                                                         \
        _Pragma("unroll")                                                     \
        for (int i = 0; i < 2; i++) {                                         \
            int idx = tid * 2 + i; int r = idx >> 2, kc = idx & 3;            \
            pa[i] = *reinterpret_cast<const float4*>(                         \
                A + (size_t)(row0 + r) * K + (k0) + kc * 4);                  \
            int rb = col0 + r;                                                \
            if (rb < N)                                                       \
                pb[i] = *reinterpret_cast<const float4*>(                     \
                    Bt + (size_t)rb * K + (k0) + kc * 4);                     \
            else                                                              \
                pb[i] = make_float4(0.f, 0.f, 0.f, 0.f);                      \
        }                                                                     \
    }
#define STST()                                                                \
    {                                                                         \
        _Pragma("unroll")                                                     \
        for (int i = 0; i < 2; i++) {                                         \
            int idx = tid * 2 + i; int r = idx >> 2, kc = idx & 3;            \
            __half2 a0 = __floats2half2_rn(pa[i].x, pa[i].y);                 \
            __half2 a1 = __floats2half2_rn(pa[i].z, pa[i].w);                 \
            __half2 b0 = __floats2half2_rn(pb[i].x, pb[i].y);                 \
            __half2 b1 = __floats2half2_rn(pb[i].z, pb[i].w);                 \
            *reinterpret_cast<__half2*>(&As[r * HSTR + kc * 4])     = a0;     \
            *reinterpret_cast<__half2*>(&As[r * HSTR + kc * 4 + 2]) = a1;     \
            *reinterpret_cast<__half2*>(&Bs[r * HSTR + kc * 4])     = b0;     \
            *reinterpret_cast<__half2*>(&Bs[r * HSTR + kc * 4 + 2]) = b1;     \
        }                                                                     \
    }

    LOADT(0);
    for (int kt = 0; kt < KT; kt++) {
        STST();
        __syncthreads();
        if (kt + 1 < KT) LOADT((kt + 1) * 16);

        const int g   = lane >> 2;
        const int kq2 = (lane & 3) * 2;
        unsigned af[4][4], bf[4][2];
#pragma unroll
        for (int mf = 0; mf < 4; mf++) {
            int m = wm + mf * 16 + g;
            af[mf][0] = *reinterpret_cast<const unsigned*>(&As[m * HSTR + kq2]);
            af[mf][1] = *reinterpret_cast<const unsigned*>(&As[(m + 8) * HSTR + kq2]);
            af[mf][2] = *reinterpret_cast<const unsigned*>(&As[m * HSTR + kq2 + 8]);
            af[mf][3] = *reinterpret_cast<const unsigned*>(&As[(m + 8) * HSTR + kq2 + 8]);
        }
#pragma unroll
        for (int nf = 0; nf < 4; nf++) {
            int n = wn + nf * 8 + g;
            bf[nf][0] = *reinterpret_cast<const unsigned*>(&Bs[n * HSTR + kq2]);
            bf[nf][1] = *reinterpret_cast<const unsigned*>(&Bs[n * HSTR + kq2 + 8]);
        }
#pragma unroll
        for (int mf = 0; mf < 4; mf++)
#pragma unroll
            for (int nf = 0; nf < 4; nf++)
                asm volatile(
                    "mma.sync.aligned.m16n8k16.row.col.f32.f16.f16.f32 "
                    "{%0,%1,%2,%3}, {%4,%5,%6,%7}, {%8,%9}, {%0,%1,%2,%3};"
                    : "+f"(acc[mf][nf][0]), "+f"(acc[mf][nf][1]),
                      "+f"(acc[mf][nf][2]), "+f"(acc[mf][nf][3])
                    : "r"(af[mf][0]), "r"(af[mf][1]), "r"(af[mf][2]), "r"(af[mf][3]),
                      "r"(bf[nf][0]), "r"(bf[nf][1]));
        __syncthreads();
    }

    // epilogue: c0=(r,n) c1=(r,n+1) c2=(r+8,n) c3=(r+8,n+1)
#pragma unroll
    for (int mf = 0; mf < 4; mf++) {
        int r0 = row0 + wm + mf * 16 + (lane >> 2);
#pragma unroll
        for (int nf = 0; nf < 4; nf++) {
            int n0 = col0 + wn + nf * 8 + 2 * (lane & 3);
#pragma unroll
            for (int half = 0; half < 2; half++) {
                int r = r0 + half * 8;
#pragma unroll
                for (int j = 0; j < 2; j++) {
                    int n = n0 + j;
                    if (n < N) {
                        float v = acc[mf][nf][half * 2 + j];
                        if (EPI & 1) v += bias[n];
                        if (EPI & 2) v = fmaxf(v, 0.0f);
                        if (EPI & 4) v += resid[(size_t)r * N + n];
                        C[(size_t)r * N + n] = v;
                    }
                }
            }
        }
    }
#undef LOADT
#undef STST
}

// ---------------- streaming causal attention (warp = 4 queries) ------------
__global__ __launch_bounds__(256)
void attn_kernel(const float* __restrict__ qkv, float* __restrict__ o) {
    int wid = blockIdx.x * 8 + (threadIdx.x >> 5);
    int lane = threadIdx.x & 31;
    const int warps_per_head = NT / 4;  // 512
    int bh = wid / warps_per_head;
    int t0 = (wid % warps_per_head) * 4;
    int b = bh / NH, h = bh % NH;

    const float* base = qkv + (size_t)b * NT * NQKV;
    const float* qb = base + h * NHS;
    const float* kb = base + ND + h * NHS;
    const float* vb = base + 2 * ND + h * NHS;

    float q0[4], q1[4];
#pragma unroll
    for (int i = 0; i < 4; i++) {
        q0[i] = qb[(size_t)(t0 + i) * NQKV + lane];
        q1[i] = qb[(size_t)(t0 + i) * NQKV + 32 + lane];
    }
    float m[4], l[4], a0[4], a1[4];
#pragma unroll
    for (int i = 0; i < 4; i++) { m[i] = -1e30f; l[i] = 0.f; a0[i] = 0.f; a1[i] = 0.f; }

    const float scale = 0.125f;
    int send = t0 + 3;
    for (int s = 0; s <= send; s++) {
        size_t off = (size_t)s * NQKV + lane;
        float k0v = kb[off], k1v = kb[off + 32];
        float v0v = vb[off], v1v = vb[off + 32];
#pragma unroll
        for (int i = 0; i < 4; i++) {
            float p = q0[i] * k0v + q1[i] * k1v;
            p += __shfl_xor_sync(0xffffffffu, p, 16);
            p += __shfl_xor_sync(0xffffffffu, p, 8);
            p += __shfl_xor_sync(0xffffffffu, p, 4);
            p += __shfl_xor_sync(0xffffffffu, p, 2);
            p += __shfl_xor_sync(0xffffffffu, p, 1);
            if (s <= t0 + i) {
                float sc = p * scale;
                float mn = fmaxf(m[i], sc);
                float corr = __expf(m[i] - mn);
                float e = __expf(sc - mn);
                l[i]  = l[i]  * corr + e;
                a0[i] = a0[i] * corr + e * v0v;
                a1[i] = a1[i] * corr + e * v1v;
                m[i] = mn;
            }
        }
    }
#pragma unroll
    for (int i = 0; i < 4; i++) {
        size_t oo = (size_t)(b * NT + t0 + i) * ND + h * NHS + lane;
        o[oo]      = a0[i] / l[i];
        o[oo + 32] = a1[i] / l[i];
    }
}

// ---------------- loss ------------------------------------------------------
__global__ __launch_bounds__(256)
void loss_kernel(const float* __restrict__ logits, const int* __restrict__ targets) {
    __shared__ float sm_[256], sl_[256];
    int row = blockIdx.x, tid = threadIdx.x;
    const float* lr = logits + (size_t)row * NV;
    float m = -1e30f, l = 0.0f;
    for (int j = tid; j < NV; j += 256) {
        float v = lr[j];
        float mn = fmaxf(m, v);
        l = l * __expf(m - mn) + __expf(v - mn);
        m = mn;
    }
    sm_[tid] = m; sl_[tid] = l;
    __syncthreads();
    for (int off = 128; off; off >>= 1) {
        if (tid < off) {
            float m2 = sm_[tid + off], l2 = sl_[tid + off];
            float mn = fmaxf(sm_[tid], m2);
            sl_[tid] = sl_[tid] * __expf(sm_[tid] - mn) + l2 * __expf(m2 - mn);
            sm_[tid] = mn;
        }
        __syncthreads();
    }
    if (tid == 0) {
        float lp = lr[targets[row]] - sm_[0] - logf(sl_[0]);
        atomicAdd(&g_loss, -lp * (1.0f / NTOK));
    }
}

__global__ void finalize_loss_kernel(float* out, int out_size) {
    long long pos = (long long)NTOK * NV;
    if ((long long)out_size > pos) out[pos] = g_loss;
}

// ---------------- host orchestration ----------------------------------------
extern "C" void kernel_launch(void* const* d_in, const int* in_sizes, int n_in,
                              void* d_out, int out_size) {
    const int*   idx     = (const int*)d_in[0];
    const int*   targets = (const int*)d_in[1];
    const float* tok_emb = (const float*)d_in[2];
    const float* pos_emb = (const float*)d_in[3];
    const float* wq      = (const float*)d_in[4];
    const float* wk      = (const float*)d_in[5];
    const float* wv      = (const float*)d_in[6];
    const float* wo      = (const float*)d_in[7];
    const float* bo      = (const float*)d_in[8];
    const float* ln1_s   = (const float*)d_in[9];
    const float* ln1_b   = (const float*)d_in[10];
    const float* ln2_s   = (const float*)d_in[11];
    const float* ln2_b   = (const float*)d_in[12];
    const float* w1      = (const float*)d_in[13];
    const float* b1      = (const float*)d_in[14];
    const float* w2      = (const float*)d_in[15];
    const float* b2      = (const float*)d_in[16];
    const float* lnf_s   = (const float*)d_in[17];
    const float* lnf_b   = (const float*)d_in[18];
    const float* head_w  = (const float*)d_in[19];
    const float* head_b  = (const float*)d_in[20];
    float* out = (float*)d_out;
    (void)in_sizes; (void)n_in;

    float *px, *ph, *pqkv, *po, *pmlp;
    float *pwqkvT, *pwoT, *pw1T, *pw2T, *pheadT;
    cudaGetSymbolAddress((void**)&px,     g_x);
    cudaGetSymbolAddress((void**)&ph,     g_h);
    cudaGetSymbolAddress((void**)&pqkv,   g_qkv);
    cudaGetSymbolAddress((void**)&po,     g_o);
    cudaGetSymbolAddress((void**)&pmlp,   g_mlp);
    cudaGetSymbolAddress((void**)&pwqkvT, g_wqkvT);
    cudaGetSymbolAddress((void**)&pwoT,   g_woT);
    cudaGetSymbolAddress((void**)&pw1T,   g_w1T);
    cudaGetSymbolAddress((void**)&pw2T,   g_w2T);
    cudaGetSymbolAddress((void**)&pheadT, g_headT);

    reset_loss_kernel<<<1, 1>>>();
    {
        int total = NL * NQKV * ND;
        repack_qkv_kernel<<<(total + 255) / 256, 256>>>(wq, wk, wv);
    }
    {
        dim3 blk(32, 8);
        transpose_kernel<<<dim3(24, 24, NL), blk>>>(wo, pwoT, ND, ND);
        transpose_kernel<<<dim3(96, 24, NL), blk>>>(w1, pw1T, ND, NFF);
        transpose_kernel<<<dim3(24, 96, NL), blk>>>(w2, pw2T, NFF, ND);
        transpose_kernel<<<dim3((NV + 31) / 32, 24, 1), blk>>>(head_w, pheadT, ND, NV);
    }
    {
        int total = NTOK * ND;
        embed_kernel<<<(total + 255) / 256, 256>>>(idx, tok_emb, pos_emb);
    }

    // grid: x = M panels (fast) -> B column panel reused across a wave
    dim3 gQKV(NTOK / 128, NQKV / 128);
    dim3 gD(NTOK / 128, ND / 128);
    dim3 gFF(NTOK / 128, NFF / 128);
    dim3 gV(NTOK / 128, (NV + 127) / 128);

    for (int l = 0; l < NL; l++) {
        ln_kernel<<<NTOK, 256>>>(px, ln1_s + l * ND, ln1_b + l * ND, ph);
        hgemm<0><<<gQKV, 256>>>(ph, pwqkvT + (size_t)l * NQKV * ND,
                                nullptr, nullptr, pqkv, NTOK, NQKV, ND);
        attn_kernel<<<NB * NH * NT / 4 / 8, 256>>>(pqkv, po);
        hgemm<5><<<gD, 256>>>(po, pwoT + (size_t)l * ND * ND,
                              bo + l * ND, px, px, NTOK, ND, ND);
        ln_kernel<<<NTOK, 256>>>(px, ln2_s + l * ND, ln2_b + l * ND, ph);
        hgemm<3><<<gFF, 256>>>(ph, pw1T + (size_t)l * ND * NFF,
                               b1 + l * NFF, nullptr, pmlp, NTOK, NFF, ND);
        hgemm<5><<<gD, 256>>>(pmlp, pw2T + (size_t)l * NFF * ND,
                              b2 + l * ND, px, px, NTOK, ND, NFF);
    }

    ln_kernel<<<NTOK, 256>>>(px, lnf_s, lnf_b, ph);
    hgemm<1><<<gV, 256>>>(ph, pheadT, head_b, nullptr, out, NTOK, NV, ND);
    loss_kernel<<<NTOK, 256>>>(out, targets);
    finalize_loss_kernel<<<1, 1>>>(out, out_size);
}